// round 10
// baseline (speedup 1.0000x reference)
#include <cuda_runtime.h>
#include <math.h>
#include <stdint.h>

#define BB    256
#define NN    32
#define FF    40
#define HH    100
#define MM    100
#define EFN   4
#define OUTD  128
#define H3    300
#define KMAX  8
#define NODES (BB*NN)   // 8192
#define TPAD  40        // T row stride (floats)
#define NTHR  416
#define KTILE 8         // GRU k-tile
#define NTILE 13        // ceil(100/8)

typedef unsigned long long ull;
typedef unsigned int u32;

// ---------------- device scratch ----------------
__device__ __align__(16) float g_Wm[EFN*HH*MM];      // [f][k][m]
__device__ __align__(16) float g_Wph[HH*50*12];      // [k][hp][12]: ihR01,ihZ01,ihN01,hhR01,hhZ01,hhN01
__device__ __align__(16) ulonglong2 g_WgeD[140*HH];  // [k][h] = {dup(wg), dup(we)}
__device__ int   g_nbr[NODES*KMAX];
__device__ int   g_typ[NODES*KMAX];
__device__ float g_wgt[NODES*KMAX];
__device__ int   g_cnt[NODES];

__device__ __forceinline__ float sigmf(float x) { return 1.0f / (1.0f + expf(-x)); }
__device__ __forceinline__ ull packdup(float w) {
    ull r; asm("mov.b64 %0,{%1,%1};" : "=l"(r) : "f"(w)); return r;
}
__device__ __forceinline__ ull pack2(float lo, float hi) {
    ull r; asm("mov.b64 %0,{%1,%2};" : "=l"(r) : "f"(lo), "f"(hi)); return r;
}
__device__ __forceinline__ void unpack2(ull v, float& lo, float& hi) {
    asm("mov.b64 {%0,%1},%2;" : "=f"(lo), "=f"(hi) : "l"(v));
}
__device__ __forceinline__ void fma2(ull& d, ull a, ull b) {
    asm("fma.rn.f32x2 %0, %1, %2, %0;" : "+l"(d) : "l"(a), "l"(b));
}
__device__ __forceinline__ void cpasync16(u32 dst, const void* src) {
    asm volatile("cp.async.ca.shared.global [%0], [%1], 16;" :: "r"(dst), "l"(src) : "memory");
}
__device__ __forceinline__ void cpcommit() { asm volatile("cp.async.commit_group;" ::: "memory"); }
__device__ __forceinline__ void cpwait0()  { asm volatile("cp.async.wait_group 0;" ::: "memory"); }

// ---------------- prep: weight layouts ----------------
__global__ void prep_weights(const float* __restrict__ W_msg,
                             const float* __restrict__ W_ih,
                             const float* __restrict__ W_hh,
                             const float* __restrict__ Wg,
                             const float* __restrict__ We) {
    int gid = blockIdx.x * blockDim.x + threadIdx.x;
    const int NWT = EFN*HH*MM;            // 40000
    const int NWP = HH*50*12;             // 60000
    if (gid < NWT) {
        int f = gid / (HH*MM);
        int rem = gid % (HH*MM);
        int k = rem / MM;
        int m = rem % MM;
        g_Wm[gid] = W_msg[(m*HH + k)*EFN + f];
    } else if (gid < NWT + NWP) {
        int t = gid - NWT;
        int k = t / 600;
        int r = t % 600;
        int hp = r / 12, q = r % 12;
        int gate = q >> 1, par = q & 1;
        int h = 2*hp + par;
        float v;
        if (gate < 3) v = W_ih[(gate*100 + h)*HH + k];
        else          v = W_hh[((gate-3)*100 + h)*HH + k];
        g_Wph[t] = v;
    } else if (gid < NWT + NWP + 140*HH) {
        int t = gid - NWT - NWP;
        int k = t / HH, h = t % HH;
        float wg = Wg[k*HH + h];
        float we = (k < HH) ? We[k*HH + h] : 0.0f;
        g_WgeD[t] = make_ulonglong2(packdup(wg), packdup(we));
    }
}

// ---------------- prep: compact edge lists (warp per node) ----------------
__global__ void prep_edges(const float* __restrict__ edges) {
    int warp = (blockIdx.x * blockDim.x + threadIdx.x) >> 5;
    int lane = threadIdx.x & 31;
    if (warp >= NODES) return;
    int p = warp;
    float4 v = ((const float4*)edges)[(size_t)p * NN + lane];
    float vv[4] = {v.x, v.y, v.z, v.w};
    int nl = (vv[0]!=0.f) + (vv[1]!=0.f) + (vv[2]!=0.f) + (vv[3]!=0.f);
    int inc = nl;
    #pragma unroll
    for (int off = 1; off < 32; off <<= 1) {
        int t = __shfl_up_sync(0xFFFFFFFFu, inc, off);
        if (lane >= off) inc += t;
    }
    int excl = inc - nl;
    int total = __shfl_sync(0xFFFFFFFFu, inc, 31);
    int c = excl;
    #pragma unroll
    for (int f = 0; f < EFN; f++) {
        if (vv[f] != 0.f && c < KMAX) {
            g_nbr[p*KMAX + c] = lane;
            g_typ[p*KMAX + c] = f;
            g_wgt[p*KMAX + c] = vv[f];
            c++;
        }
    }
    if (lane == 0) g_cnt[p] = (total < KMAX) ? total : KMAX;
}

// ---------------- fused: 3 passes + readout, one block per batch ----------
__global__ __launch_bounds__(NTHR, 2) void fused_kernel(
        const float* __restrict__ nodes,
        const float* __restrict__ b_ih, const float* __restrict__ b_hh,
        const float* __restrict__ bg,   const float* __restrict__ be,
        const float* __restrict__ Wo,   const float* __restrict__ bo,
        float* __restrict__ out) {
    __shared__ __align__(16) float sh_h[HH*NN];          // [k][n] 12.8KB
    __shared__ __align__(16) float sh_T[EFN*HH*TPAD];    // 64KB: T / (msgD + weight bufs) / readout scratch
    __shared__ __align__(16) ull   sh_hD[HH*NN];         // dup'd hidden [k][n] 25.6KB
    __shared__ int   sh_nbr[NN][KMAX];
    __shared__ int   sh_typ[NN][KMAX];
    __shared__ float sh_wgt[NN][KMAX];
    __shared__ int   sh_cnt[NN];

    const int b   = blockIdx.x;
    const int tid = threadIdx.x;
    const int p0  = b * NN;

    // overlays inside sh_T during GRU phase
    ull*   msgD  = (ull*)sh_T;                 // [k][n] dup'd msgs: 3200 ull = 25.6KB
    float* wbufs = sh_T + 6400;                // two KTILE*50*12-float buffers (2*4800 floats)

    // edge meta
    if (tid < NN) sh_cnt[tid] = g_cnt[p0 + tid];
    else if (tid >= 32 && tid < 32 + NN*KMAX) {
        int t = tid - 32; int n = t >> 3, e = t & 7;
        sh_nbr[n][e] = g_nbr[(p0+n)*KMAX + e];
        sh_typ[n][e] = g_typ[(p0+n)*KMAX + e];
        sh_wgt[n][e] = g_wgt[(p0+n)*KMAX + e];
    }
    // hidden init: [nodes | 0] in both layouts
    for (int idx = tid; idx < HH*NN; idx += NTHR) {
        int k = idx >> 5, n = idx & 31;
        float v = (k < FF) ? nodes[(size_t)(p0+n)*FF + k] : 0.0f;
        sh_h[idx]  = v;
        sh_hD[idx] = packdup(v);
    }
    __syncthreads();

    // GRU thread mapping: h-pair x 4-node group
    const int hp  = (tid < 400) ? (tid >> 3) : 0;    // 0..49
    const int ngr = (tid < 400) ? (tid & 7)  : 0;    // 0..7 (4 nodes each)
    // hoisted biases for this h-pair
    float brz0=0, bzz0=0, bin0=0, bhn0=0, brz1=0, bzz1=0, bin1=0, bhn1=0;
    if (tid < 400) {
        int h0 = 2*hp, h1 = h0 + 1;
        brz0 = b_ih[h0] + b_hh[h0];          brz1 = b_ih[h1] + b_hh[h1];
        bzz0 = b_ih[100+h0] + b_hh[100+h0];  bzz1 = b_ih[100+h1] + b_hh[100+h1];
        bin0 = b_ih[200+h0];                 bin1 = b_ih[200+h1];
        bhn0 = b_hh[200+h0];                 bhn1 = b_hh[200+h1];
    }

    for (int pass = 0; pass < 3; pass++) {
        // ---- T[f][m][n] = sum_k Wm[f][k][m] * h[k][n] ----
        if (tid < 400) {
            const int f = tid / 100, m = tid - f*100;
            ull acc[16];
            #pragma unroll
            for (int j = 0; j < 16; j++) acc[j] = 0ull;
            const float* W = g_Wm + (size_t)(f*HH)*MM + m;
            for (int k = 0; k < HH; k++) {
                ull w = packdup(W[k*MM]);
                const ulonglong2* hp2 = (const ulonglong2*)(sh_h + k*NN);
                ulonglong2 v0 = hp2[0], v1 = hp2[1], v2 = hp2[2], v3 = hp2[3];
                fma2(acc[0], w, v0.x); fma2(acc[1], w, v0.y);
                fma2(acc[2], w, v1.x); fma2(acc[3], w, v1.y);
                fma2(acc[4], w, v2.x); fma2(acc[5], w, v2.y);
                fma2(acc[6], w, v3.x); fma2(acc[7], w, v3.y);
                ulonglong2 v4 = hp2[4], v5 = hp2[5], v6 = hp2[6], v7 = hp2[7];
                fma2(acc[8],  w, v4.x); fma2(acc[9],  w, v4.y);
                fma2(acc[10], w, v5.x); fma2(acc[11], w, v5.y);
                fma2(acc[12], w, v6.x); fma2(acc[13], w, v6.y);
                fma2(acc[14], w, v7.x); fma2(acc[15], w, v7.y);
            }
            ulonglong2* Trow = (ulonglong2*)(sh_T + (size_t)(f*MM + m)*TPAD);
            #pragma unroll
            for (int j = 0; j < 8; j++) Trow[j] = make_ulonglong2(acc[2*j], acc[2*j+1]);
        }
        __syncthreads();

        // ---- gather to regs: msg[m][n] = sum_e w_e * T[f_e][m][g_e] ----
        float res[8];
        if (tid < 400) {
            const int m = tid >> 2;
            const int n0 = (tid & 3) * 8;
            #pragma unroll
            for (int j = 0; j < 8; j++) {
                int n = n0 + j;
                int c = sh_cnt[n];
                float s = 0.f;
                for (int e = 0; e < c; e++) {
                    s += sh_wgt[n][e] *
                         sh_T[(size_t)(sh_typ[n][e]*MM + m)*TPAD + sh_nbr[n][e]];
                }
                res[j] = s;
            }
        }
        __syncthreads();   // all T reads done; sh_T now reusable

        // store dup'd msgs + prefetch GRU weight tile 0
        if (tid < 400) {
            const int m = tid >> 2;
            const int n0 = (tid & 3) * 8;
            #pragma unroll
            for (int j = 0; j < 8; j++)
                msgD[m*NN + n0 + j] = packdup(res[j]);
        }
        {
            u32 dstb = (u32)__cvta_generic_to_shared(wbufs);
            const float4* src = (const float4*)g_Wph;
            for (int i = tid; i < KTILE*150; i += NTHR)   // KTILE*50*12 floats = KTILE*150 float4
                cpasync16(dstb + i*16, src + i);
            cpcommit();
        }

        // ---- GRU: (h-pair, 4 nodes) threads; dup'd data; mov-free loop ----
        ull accR[4], accZ[4], accNi[4], accNh[4];
        #pragma unroll
        for (int j = 0; j < 4; j++) { accR[j]=0; accZ[j]=0; accNi[j]=0; accNh[j]=0; }

        for (int t = 0; t < NTILE; t++) {
            const int kbase = t * KTILE;
            const int kt = (HH - kbase < KTILE) ? (HH - kbase) : KTILE;
            float* buf = wbufs + (t & 1) * (KTILE*600);
            cpwait0();
            __syncthreads();
            if (t + 1 < NTILE) {
                const int nb = (t+1) * KTILE;
                const int nkt = (HH - nb < KTILE) ? (HH - nb) : KTILE;
                float* nbuf = wbufs + ((t+1) & 1) * (KTILE*600);
                u32 dstb = (u32)__cvta_generic_to_shared(nbuf);
                const float4* src = (const float4*)(g_Wph + (size_t)nb*600);
                for (int i = tid; i < nkt*150; i += NTHR)
                    cpasync16(dstb + i*16, src + i);
                cpcommit();
            }
            if (tid < 400) {
                for (int kk = 0; kk < kt; kk++) {
                    const int k = kbase + kk;
                    const ulonglong2* wp = (const ulonglong2*)(buf + kk*600 + hp*12);
                    ulonglong2 wa = wp[0];   // {ihR, ihZ} h-pairs
                    ulonglong2 wb = wp[1];   // {ihN, hhR}
                    ulonglong2 wc = wp[2];   // {hhZ, hhN}
                    const ulonglong2* mp = (const ulonglong2*)(msgD + k*NN + ngr*4);
                    const ulonglong2* hd = (const ulonglong2*)(sh_hD + k*NN + ngr*4);
                    ulonglong2 m01 = mp[0], m23 = mp[1];
                    ulonglong2 h01 = hd[0], h23 = hd[1];
                    fma2(accR[0], wa.x, m01.x); fma2(accR[0], wb.y, h01.x);
                    fma2(accR[1], wa.x, m01.y); fma2(accR[1], wb.y, h01.y);
                    fma2(accR[2], wa.x, m23.x); fma2(accR[2], wb.y, h23.x);
                    fma2(accR[3], wa.x, m23.y); fma2(accR[3], wb.y, h23.y);
                    fma2(accZ[0], wa.y, m01.x); fma2(accZ[0], wc.x, h01.x);
                    fma2(accZ[1], wa.y, m01.y); fma2(accZ[1], wc.x, h01.y);
                    fma2(accZ[2], wa.y, m23.x); fma2(accZ[2], wc.x, h23.x);
                    fma2(accZ[3], wa.y, m23.y); fma2(accZ[3], wc.x, h23.y);
                    fma2(accNi[0], wb.x, m01.x); fma2(accNi[1], wb.x, m01.y);
                    fma2(accNi[2], wb.x, m23.x); fma2(accNi[3], wb.x, m23.y);
                    fma2(accNh[0], wc.y, h01.x); fma2(accNh[1], wc.y, h01.y);
                    fma2(accNh[2], wc.y, h23.x); fma2(accNh[3], wc.y, h23.y);
                }
            }
        }

        // previous h for this (h-pair, 4 nodes) — read BEFORE the write barrier
        float hv0[4], hv1[4];
        if (tid < 400) {
            #pragma unroll
            for (int j = 0; j < 4; j++) {
                int n = ngr*4 + j;
                hv0[j] = sh_h[(2*hp)*NN + n];
                hv1[j] = sh_h[(2*hp+1)*NN + n];
            }
        }
        __syncthreads();   // all GRU reads of sh_h/sh_hD/msgD done

        if (tid < 400) {
            #pragma unroll
            for (int j = 0; j < 4; j++) {
                int n = ngr*4 + j;
                float r0a, r1a, z0a, z1a, ni0, ni1, nh0, nh1;
                unpack2(accR[j],  r0a, r1a);
                unpack2(accZ[j],  z0a, z1a);
                unpack2(accNi[j], ni0, ni1);
                unpack2(accNh[j], nh0, nh1);
                float o0 = hv0[j], o1 = hv1[j];
                if (sh_cnt[n] != 0) {
                    float r = sigmf(r0a + brz0);
                    float z = sigmf(z0a + bzz0);
                    float nv = tanhf(ni0 + bin0 + r*(nh0 + bhn0));
                    o0 = (1.0f - z)*nv + z*o0;
                    r = sigmf(r1a + brz1);
                    z = sigmf(z1a + bzz1);
                    nv = tanhf(ni1 + bin1 + r*(nh1 + bhn1));
                    o1 = (1.0f - z)*nv + z*o1;
                }
                sh_h[(2*hp)*NN + n]   = o0;
                sh_h[(2*hp+1)*NN + n] = o1;
                sh_hD[(2*hp)*NN + n]   = packdup(o0);
                sh_hD[(2*hp+1)*NN + n] = packdup(o1);
            }
        }
        __syncthreads();
    }

    // ---- readout (scratch overlaid in sh_T) ----
    float* sh_x    = sh_T;           // [FF][NN] 1280 floats
    float* sh_part = sh_T + 1280;    // 400 floats
    float* sh_acc  = sh_T + 1680;    // 100 floats
    for (int idx = tid; idx < NN*FF; idx += NTHR) {
        int n = idx / FF, k = idx % FF;
        sh_x[k*NN + n] = nodes[(size_t)(p0+n)*FF + k];
    }
    __syncthreads();

    if (tid < 400) {
        const int hh2 = tid % 100;
        const int ng2 = tid / 100;
        ull ga[4], ev[4];
        #pragma unroll
        for (int j = 0; j < 4; j++) { ga[j] = 0; ev[j] = 0; }
        const ulonglong2* WD = g_WgeD + hh2;
        for (int k = 0; k < HH; k++) {
            ulonglong2 w = WD[k*HH];
            const ulonglong2* hp2 = (const ulonglong2*)(sh_h + k*NN + ng2*8);
            ulonglong2 a = hp2[0], c = hp2[1];
            fma2(ga[0], w.x, a.x); fma2(ga[1], w.x, a.y);
            fma2(ga[2], w.x, c.x); fma2(ga[3], w.x, c.y);
            fma2(ev[0], w.y, a.x); fma2(ev[1], w.y, a.y);
            fma2(ev[2], w.y, c.x); fma2(ev[3], w.y, c.y);
        }
        for (int k = 0; k < FF; k++) {
            ulonglong2 w = WD[(HH + k)*HH];
            const ulonglong2* xp = (const ulonglong2*)(sh_x + k*NN + ng2*8);
            ulonglong2 a = xp[0], c = xp[1];
            fma2(ga[0], w.x, a.x); fma2(ga[1], w.x, a.y);
            fma2(ga[2], w.x, c.x); fma2(ga[3], w.x, c.y);
        }
        float bgv = bg[hh2], bev = be[hh2];
        float s = 0.f;
        #pragma unroll
        for (int j = 0; j < 4; j++) {
            float gl, gh_, el, eh;
            unpack2(ga[j], gl, gh_);
            unpack2(ev[j], el, eh);
            int nA = ng2*8 + 2*j, nB = nA + 1;
            if (sh_cnt[nA] != 0) s += sigmf(gl + bgv) * (el + bev);
            if (sh_cnt[nB] != 0) s += sigmf(gh_ + bgv) * (eh + bev);
        }
        sh_part[ng2*HH + hh2] = s;
    }
    __syncthreads();
    if (tid < HH)
        sh_acc[tid] = sh_part[tid] + sh_part[HH + tid] + sh_part[2*HH + tid] + sh_part[3*HH + tid];
    __syncthreads();

    if (tid < OUTD) {
        float v = bo[tid];
        #pragma unroll 4
        for (int k = 0; k < HH; k++) v += sh_acc[k] * Wo[k*OUTD + tid];
        out[(size_t)b*OUTD + tid] = v;
    }
}

// ---------------- launcher ----------------
extern "C" void kernel_launch(void* const* d_in, const int* in_sizes, int n_in,
                              void* d_out, int out_size) {
    const float* nodes = (const float*)d_in[0];
    const float* edges = (const float*)d_in[1];
    const float* W_msg = (const float*)d_in[2];
    const float* W_ih  = (const float*)d_in[3];
    const float* W_hh  = (const float*)d_in[4];
    const float* b_ih  = (const float*)d_in[5];
    const float* b_hh  = (const float*)d_in[6];
    const float* Wg    = (const float*)d_in[7];
    const float* bg    = (const float*)d_in[8];
    const float* We    = (const float*)d_in[9];
    const float* be    = (const float*)d_in[10];
    const float* Wo    = (const float*)d_in[11];
    const float* bo    = (const float*)d_in[12];
    float* out = (float*)d_out;

    prep_weights<<<(114000 + 255) / 256, 256>>>(W_msg, W_ih, W_hh, Wg, We);
    prep_edges<<<(NODES*32 + 255) / 256, 256>>>(edges);
    fused_kernel<<<BB, NTHR>>>(nodes, b_ih, b_hh, bg, be, Wo, bo, out);
}

// round 11
// speedup vs baseline: 1.2719x; 1.2719x over previous
#include <cuda_runtime.h>
#include <math.h>
#include <stdint.h>

#define BB    256
#define NN    32
#define FF    40
#define HH    100
#define MM    100
#define EFN   4
#define OUTD  128
#define H3    300
#define KMAX  8
#define NODES (BB*NN)   // 8192
#define TPAD  40        // T row stride (floats)
#define NTHR  416
#define KTILE 13        // GRU k-tile
#define NTILE 8         // ceil(100/13)

typedef unsigned long long ull;
typedef unsigned int u32;

// ---------------- device scratch ----------------
__device__ __align__(16) float g_Wm[EFN*HH*MM];      // [f][k][m]
__device__ __align__(16) float g_Wp[HH*HH*6];        // [k][h][6] = ihR,ihZ,ihN,hhR,hhZ,hhN
__device__ __align__(16) ulonglong2 g_WgeD[140*HH];  // [k][h] = {dup(wg), dup(we)}
__device__ int   g_nbr[NODES*KMAX];
__device__ int   g_typ[NODES*KMAX];
__device__ float g_wgt[NODES*KMAX];
__device__ int   g_cnt[NODES];

__device__ __forceinline__ float sigmf(float x) { return 1.0f / (1.0f + expf(-x)); }
__device__ __forceinline__ ull packdup(float w) {
    ull r; asm("mov.b64 %0,{%1,%1};" : "=l"(r) : "f"(w)); return r;
}
__device__ __forceinline__ void unpack2(ull v, float& lo, float& hi) {
    asm("mov.b64 {%0,%1},%2;" : "=f"(lo), "=f"(hi) : "l"(v));
}
__device__ __forceinline__ void fma2(ull& d, ull a, ull b) {
    asm("fma.rn.f32x2 %0, %1, %2, %0;" : "+l"(d) : "l"(a), "l"(b));
}
__device__ __forceinline__ void cpasync16(u32 dst, const void* src) {
    asm volatile("cp.async.ca.shared.global [%0], [%1], 16;" :: "r"(dst), "l"(src) : "memory");
}
__device__ __forceinline__ void cpcommit() { asm volatile("cp.async.commit_group;" ::: "memory"); }
__device__ __forceinline__ void cpwait0()  { asm volatile("cp.async.wait_group 0;" ::: "memory"); }

// ---------------- prep kernels (split so fused_kernel is eager-launch #5) ----
__global__ void prep_wm(const float* __restrict__ W_msg) {
    int gid = blockIdx.x * blockDim.x + threadIdx.x;
    if (gid >= EFN*HH*MM) return;
    int f = gid / (HH*MM);
    int rem = gid % (HH*MM);
    int k = rem / MM;
    int m = rem % MM;
    g_Wm[gid] = W_msg[(m*HH + k)*EFN + f];
}

__global__ void prep_wp_lo(const float* __restrict__ W_ih,
                           const float* __restrict__ W_hh) {
    int t = blockIdx.x * blockDim.x + threadIdx.x;   // (k,h) for k < 50
    if (t >= 50*HH) return;
    int k = t / HH, h = t % HH;
    float* dst = g_Wp + (size_t)t*6;
    dst[0] = W_ih[(h)*HH + k];
    dst[1] = W_ih[(100+h)*HH + k];
    dst[2] = W_ih[(200+h)*HH + k];
    dst[3] = W_hh[(h)*HH + k];
    dst[4] = W_hh[(100+h)*HH + k];
    dst[5] = W_hh[(200+h)*HH + k];
}

__global__ void prep_wp_hi(const float* __restrict__ W_ih,
                           const float* __restrict__ W_hh) {
    int t0 = blockIdx.x * blockDim.x + threadIdx.x;
    if (t0 >= 50*HH) return;
    int t = t0 + 50*HH;                              // (k,h) for k >= 50
    int k = t / HH, h = t % HH;
    float* dst = g_Wp + (size_t)t*6;
    dst[0] = W_ih[(h)*HH + k];
    dst[1] = W_ih[(100+h)*HH + k];
    dst[2] = W_ih[(200+h)*HH + k];
    dst[3] = W_hh[(h)*HH + k];
    dst[4] = W_hh[(100+h)*HH + k];
    dst[5] = W_hh[(200+h)*HH + k];
}

__global__ void prep_wge(const float* __restrict__ Wg,
                         const float* __restrict__ We) {
    int t = blockIdx.x * blockDim.x + threadIdx.x;
    if (t >= 140*HH) return;
    int k = t / HH, h = t % HH;
    float wg = Wg[k*HH + h];
    float we = (k < HH) ? We[k*HH + h] : 0.0f;
    g_WgeD[t] = make_ulonglong2(packdup(wg), packdup(we));
}

// ---------------- prep: compact edge lists (warp per node) ----------------
__global__ void prep_edges(const float* __restrict__ edges) {
    int warp = (blockIdx.x * blockDim.x + threadIdx.x) >> 5;
    int lane = threadIdx.x & 31;
    if (warp >= NODES) return;
    int p = warp;
    float4 v = ((const float4*)edges)[(size_t)p * NN + lane];
    float vv[4] = {v.x, v.y, v.z, v.w};
    int nl = (vv[0]!=0.f) + (vv[1]!=0.f) + (vv[2]!=0.f) + (vv[3]!=0.f);
    int inc = nl;
    #pragma unroll
    for (int off = 1; off < 32; off <<= 1) {
        int t = __shfl_up_sync(0xFFFFFFFFu, inc, off);
        if (lane >= off) inc += t;
    }
    int excl = inc - nl;
    int total = __shfl_sync(0xFFFFFFFFu, inc, 31);
    int c = excl;
    #pragma unroll
    for (int f = 0; f < EFN; f++) {
        if (vv[f] != 0.f && c < KMAX) {
            g_nbr[p*KMAX + c] = lane;
            g_typ[p*KMAX + c] = f;
            g_wgt[p*KMAX + c] = vv[f];
            c++;
        }
    }
    if (lane == 0) g_cnt[p] = (total < KMAX) ? total : KMAX;
}

// ---------------- fused: 3 passes + readout, one block per batch ----------
__global__ __launch_bounds__(NTHR, 2) void fused_kernel(
        const float* __restrict__ nodes,
        const float* __restrict__ b_ih, const float* __restrict__ b_hh,
        const float* __restrict__ bg,   const float* __restrict__ be,
        const float* __restrict__ Wo,   const float* __restrict__ bo,
        float* __restrict__ out) {
    __shared__ __align__(16) float sh_h[HH*NN];          // [k][n] 12.8KB
    __shared__ __align__(16) float sh_T[EFN*HH*TPAD];    // 64KB: T; GRU weight bufs overlay
    __shared__ __align__(16) float sh_msg[HH*NN];        // [k][n] 12.8KB
    __shared__ __align__(16) float sh_x[FF*NN];          // 5.1KB
    __shared__ int   sh_nbr[NN][KMAX];
    __shared__ int   sh_typ[NN][KMAX];
    __shared__ float sh_wgt[NN][KMAX];
    __shared__ int   sh_cnt[NN];
    __shared__ float sh_part[4*HH];
    __shared__ float sh_acc[HH];

    const int b   = blockIdx.x;
    const int tid = threadIdx.x;
    const int p0  = b * NN;

    // edge meta
    if (tid < NN) sh_cnt[tid] = g_cnt[p0 + tid];
    else if (tid >= 32 && tid < 32 + NN*KMAX) {
        int t = tid - 32; int n = t >> 3, e = t & 7;
        sh_nbr[n][e] = g_nbr[(p0+n)*KMAX + e];
        sh_typ[n][e] = g_typ[(p0+n)*KMAX + e];
        sh_wgt[n][e] = g_wgt[(p0+n)*KMAX + e];
    }
    // hidden init: [nodes | 0]
    for (int idx = tid; idx < HH*NN; idx += NTHR) {
        int k = idx >> 5, n = idx & 31;
        sh_h[idx] = (k < FF) ? nodes[(size_t)(p0+n)*FF + k] : 0.0f;
    }
    __syncthreads();

    const int hh = (tid < 400) ? (tid % 100) : 0;
    const int ng = (tid < 400) ? (tid / 100) : 0;

    for (int pass = 0; pass < 3; pass++) {
        // ---- T[f][m][n] = sum_k Wm[f][k][m] * h[k][n] ----
        if (tid < 400) {
            const int f = tid / 100, m = tid - f*100;
            ull acc[16];
            #pragma unroll
            for (int j = 0; j < 16; j++) acc[j] = 0ull;
            const float* W = g_Wm + (size_t)(f*HH)*MM + m;
            for (int k = 0; k < HH; k++) {
                ull w = packdup(W[k*MM]);
                const ulonglong2* hp = (const ulonglong2*)(sh_h + k*NN);
                ulonglong2 v0 = hp[0], v1 = hp[1], v2 = hp[2], v3 = hp[3];
                fma2(acc[0], w, v0.x); fma2(acc[1], w, v0.y);
                fma2(acc[2], w, v1.x); fma2(acc[3], w, v1.y);
                fma2(acc[4], w, v2.x); fma2(acc[5], w, v2.y);
                fma2(acc[6], w, v3.x); fma2(acc[7], w, v3.y);
                ulonglong2 v4 = hp[4], v5 = hp[5], v6 = hp[6], v7 = hp[7];
                fma2(acc[8],  w, v4.x); fma2(acc[9],  w, v4.y);
                fma2(acc[10], w, v5.x); fma2(acc[11], w, v5.y);
                fma2(acc[12], w, v6.x); fma2(acc[13], w, v6.y);
                fma2(acc[14], w, v7.x); fma2(acc[15], w, v7.y);
            }
            ulonglong2* Trow = (ulonglong2*)(sh_T + (size_t)(f*MM + m)*TPAD);
            #pragma unroll
            for (int j = 0; j < 8; j++) Trow[j] = make_ulonglong2(acc[2*j], acc[2*j+1]);
        }
        __syncthreads();

        // ---- gather: msg[m][n] = sum_e w_e * T[f_e][m][g_e] -> sh_msg ----
        if (tid < 400) {
            const int m = tid >> 2;
            const int n0 = (tid & 3) * 8;
            float res[8];
            #pragma unroll
            for (int j = 0; j < 8; j++) {
                int n = n0 + j;
                int c = sh_cnt[n];
                float s = 0.f;
                for (int e = 0; e < c; e++) {
                    s += sh_wgt[n][e] *
                         sh_T[(size_t)(sh_typ[n][e]*MM + m)*TPAD + sh_nbr[n][e]];
                }
                res[j] = s;
            }
            float4* dst = (float4*)(sh_msg + (size_t)m*NN + n0);
            dst[0] = make_float4(res[0], res[1], res[2], res[3]);
            dst[1] = make_float4(res[4], res[5], res[6], res[7]);
        }
        __syncthreads();   // msg visible; sh_T free for weight buffers

        // ---- GRU: double-buffered cp.async weight tiles ----
        ull accA[4], accB[4], accC[4], accD[4];
        #pragma unroll
        for (int j = 0; j < 4; j++) { accA[j]=0; accB[j]=0; accC[j]=0; accD[j]=0; }

        // prefetch tile 0 into buf 0
        {
            u32 dstb = (u32)__cvta_generic_to_shared(sh_T);
            const float4* src = (const float4*)g_Wp;
            for (int i = tid; i < KTILE*150; i += NTHR)
                cpasync16(dstb + i*16, src + i);
            cpcommit();
        }

        for (int t = 0; t < NTILE; t++) {
            const int kbase = t * KTILE;
            const int kt = (HH - kbase < KTILE) ? (HH - kbase) : KTILE;
            float* buf = sh_T + (t & 1) * (KTILE*600);
            cpwait0();
            __syncthreads();
            if (t + 1 < NTILE) {
                const int nb = (t+1) * KTILE;
                const int nkt = (HH - nb < KTILE) ? (HH - nb) : KTILE;
                float* nbuf = sh_T + ((t+1) & 1) * (KTILE*600);
                u32 dstb = (u32)__cvta_generic_to_shared(nbuf);
                const float4* src = (const float4*)(g_Wp + (size_t)nb*600);
                for (int i = tid; i < nkt*150; i += NTHR)
                    cpasync16(dstb + i*16, src + i);
                cpcommit();
            }
            if (tid < 400) {
                for (int kk = 0; kk < kt; kk++) {
                    const int k = kbase + kk;
                    const ull* wp = (const ull*)(buf + kk*600 + hh*6);
                    ull w01 = wp[0], w23 = wp[1], w45 = wp[2];
                    float wir, wiz, win, whr, whz, whn;
                    unpack2(w01, wir, wiz);
                    unpack2(w23, win, whr);
                    unpack2(w45, whz, whn);
                    ull dIR = packdup(wir), dIZ = packdup(wiz), dIN = packdup(win);
                    ull dHR = packdup(whr), dHZ = packdup(whz), dHN = packdup(whn);
                    const ulonglong2* mp = (const ulonglong2*)(sh_msg + (size_t)k*NN + ng*8);
                    const ulonglong2* hp = (const ulonglong2*)(sh_h + k*NN + ng*8);
                    ulonglong2 m01 = mp[0], m23 = mp[1];
                    ulonglong2 h01 = hp[0], h23 = hp[1];
                    fma2(accA[0], dIR, m01.x); fma2(accA[0], dHR, h01.x);
                    fma2(accA[1], dIR, m01.y); fma2(accA[1], dHR, h01.y);
                    fma2(accA[2], dIR, m23.x); fma2(accA[2], dHR, h23.x);
                    fma2(accA[3], dIR, m23.y); fma2(accA[3], dHR, h23.y);
                    fma2(accB[0], dIZ, m01.x); fma2(accB[0], dHZ, h01.x);
                    fma2(accB[1], dIZ, m01.y); fma2(accB[1], dHZ, h01.y);
                    fma2(accB[2], dIZ, m23.x); fma2(accB[2], dHZ, h23.x);
                    fma2(accB[3], dIZ, m23.y); fma2(accB[3], dHZ, h23.y);
                    fma2(accC[0], dIN, m01.x); fma2(accC[1], dIN, m01.y);
                    fma2(accC[2], dIN, m23.x); fma2(accC[3], dIN, m23.y);
                    fma2(accD[0], dHN, h01.x); fma2(accD[1], dHN, h01.y);
                    fma2(accD[2], dHN, h23.x); fma2(accD[3], dHN, h23.y);
                }
            }
        }

        // previous h values for this (h, 8 nodes)
        ull hv[4];
        if (tid < 400) {
            const ulonglong2* hvp = (const ulonglong2*)(sh_h + hh*NN + ng*8);
            ulonglong2 a = hvp[0], c = hvp[1];
            hv[0] = a.x; hv[1] = a.y; hv[2] = c.x; hv[3] = c.y;
        }
        __syncthreads();   // all reads of sh_h / sh_msg done

        if (tid < 400) {
            const float brz = b_ih[hh]       + b_hh[hh];
            const float bzz = b_ih[100 + hh] + b_hh[100 + hh];
            const float bin = b_ih[200 + hh];
            const float bhn = b_hh[200 + hh];
            float o[8];
            #pragma unroll
            for (int j = 0; j < 4; j++) {
                float a0, a1, zb0, zb1, c0, c1, d0, d1, h0, h1;
                unpack2(accA[j], a0, a1);
                unpack2(accB[j], zb0, zb1);
                unpack2(accC[j], c0, c1);
                unpack2(accD[j], d0, d1);
                unpack2(hv[j], h0, h1);
                int nA = ng*8 + 2*j, nB = nA + 1;
                {
                    float r = sigmf(a0 + brz);
                    float z = sigmf(zb0 + bzz);
                    float nv = tanhf(c0 + bin + r*(d0 + bhn));
                    o[2*j]   = (sh_cnt[nA] == 0) ? h0 : (1.0f - z)*nv + z*h0;
                }
                {
                    float r = sigmf(a1 + brz);
                    float z = sigmf(zb1 + bzz);
                    float nv = tanhf(c1 + bin + r*(d1 + bhn));
                    o[2*j+1] = (sh_cnt[nB] == 0) ? h1 : (1.0f - z)*nv + z*h1;
                }
            }
            float4* dst = (float4*)(sh_h + hh*NN + ng*8);
            dst[0] = make_float4(o[0], o[1], o[2], o[3]);
            dst[1] = make_float4(o[4], o[5], o[6], o[7]);
        }
        __syncthreads();
    }

    // ---- readout ----
    for (int idx = tid; idx < NN*FF; idx += NTHR) {
        int n = idx / FF, k = idx % FF;
        sh_x[k*NN + n] = nodes[(size_t)(p0+n)*FF + k];
    }
    __syncthreads();

    if (tid < 400) {
        ull ga[4], ev[4];
        #pragma unroll
        for (int j = 0; j < 4; j++) { ga[j] = 0; ev[j] = 0; }
        const ulonglong2* WD = g_WgeD + hh;
        for (int k = 0; k < HH; k++) {
            ulonglong2 w = WD[k*HH];
            const ulonglong2* hp = (const ulonglong2*)(sh_h + k*NN + ng*8);
            ulonglong2 a = hp[0], c = hp[1];
            fma2(ga[0], w.x, a.x); fma2(ga[1], w.x, a.y);
            fma2(ga[2], w.x, c.x); fma2(ga[3], w.x, c.y);
            fma2(ev[0], w.y, a.x); fma2(ev[1], w.y, a.y);
            fma2(ev[2], w.y, c.x); fma2(ev[3], w.y, c.y);
        }
        for (int k = 0; k < FF; k++) {
            ulonglong2 w = WD[(HH + k)*HH];
            const ulonglong2* xp = (const ulonglong2*)(sh_x + k*NN + ng*8);
            ulonglong2 a = xp[0], c = xp[1];
            fma2(ga[0], w.x, a.x); fma2(ga[1], w.x, a.y);
            fma2(ga[2], w.x, c.x); fma2(ga[3], w.x, c.y);
        }
        float bgv = bg[hh], bev = be[hh];
        float s = 0.f;
        #pragma unroll
        for (int j = 0; j < 4; j++) {
            float gl, gh_, el, eh;
            unpack2(ga[j], gl, gh_);
            unpack2(ev[j], el, eh);
            int nA = ng*8 + 2*j, nB = nA + 1;
            if (sh_cnt[nA] != 0) s += sigmf(gl + bgv) * (el + bev);
            if (sh_cnt[nB] != 0) s += sigmf(gh_ + bgv) * (eh + bev);
        }
        sh_part[ng*HH + hh] = s;
    }
    __syncthreads();
    if (tid < HH)
        sh_acc[tid] = sh_part[tid] + sh_part[HH + tid] + sh_part[2*HH + tid] + sh_part[3*HH + tid];
    __syncthreads();

    if (tid < OUTD) {
        float v = bo[tid];
        #pragma unroll 4
        for (int k = 0; k < HH; k++) v += sh_acc[k] * Wo[k*OUTD + tid];
        out[(size_t)b*OUTD + tid] = v;
    }
}

// ---------------- launcher ----------------
extern "C" void kernel_launch(void* const* d_in, const int* in_sizes, int n_in,
                              void* d_out, int out_size) {
    const float* nodes = (const float*)d_in[0];
    const float* edges = (const float*)d_in[1];
    const float* W_msg = (const float*)d_in[2];
    const float* W_ih  = (const float*)d_in[3];
    const float* W_hh  = (const float*)d_in[4];
    const float* b_ih  = (const float*)d_in[5];
    const float* b_hh  = (const float*)d_in[6];
    const float* Wg    = (const float*)d_in[7];
    const float* bg    = (const float*)d_in[8];
    const float* We    = (const float*)d_in[9];
    const float* be    = (const float*)d_in[10];
    const float* Wo    = (const float*)d_in[11];
    const float* bo    = (const float*)d_in[12];
    float* out = (float*)d_out;

    // launches 0-4: preps; launch 5: fused (so -s 5 profiles fused_kernel)
    prep_wm   <<<(EFN*HH*MM + 255) / 256, 256>>>(W_msg);
    prep_wp_lo<<<(50*HH + 255) / 256, 256>>>(W_ih, W_hh);
    prep_wp_hi<<<(50*HH + 255) / 256, 256>>>(W_ih, W_hh);
    prep_wge  <<<(140*HH + 255) / 256, 256>>>(Wg, We);
    prep_edges<<<(NODES*32 + 255) / 256, 256>>>(edges);
    fused_kernel<<<BB, NTHR>>>(nodes, b_ih, b_hh, bg, be, Wo, bo, out);
}

// round 12
// speedup vs baseline: 1.3406x; 1.0541x over previous
#include <cuda_runtime.h>
#include <math.h>
#include <stdint.h>

#define BB    256
#define NN    32
#define FF    40
#define HH    100
#define MM    100
#define EFN   4
#define OUTD  128
#define H3    300
#define KMAX  8
#define NODES (BB*NN)   // 8192
#define TPAD  40        // T row stride (floats)
#define NTHR  416
#define KTILE 12        // GRU k-tile
#define NTILE 9         // ceil(100/12)

typedef unsigned long long ull;
typedef unsigned int u32;

// ---------------- device scratch ----------------
__device__ __align__(16) float g_Wm[EFN*HH*MM];      // [f][k][m]
__device__ __align__(16) float g_Wp[HH*HH*6];        // [k][h][6] = ihR,ihZ,ihN,hhR,hhZ,hhN
__device__ __align__(16) ulonglong2 g_WgeD[140*HH];  // [k][h] = {dup(wg), dup(we)}
__device__ int   g_nbr[NODES*KMAX];
__device__ int   g_typ[NODES*KMAX];
__device__ float g_wgt[NODES*KMAX];
__device__ int   g_cnt[NODES];

__device__ __forceinline__ float sigmf(float x) { return 1.0f / (1.0f + expf(-x)); }
__device__ __forceinline__ ull packdup(float w) {
    ull r; asm("mov.b64 %0,{%1,%1};" : "=l"(r) : "f"(w)); return r;
}
__device__ __forceinline__ void unpack2(ull v, float& lo, float& hi) {
    asm("mov.b64 {%0,%1},%2;" : "=f"(lo), "=f"(hi) : "l"(v));
}
__device__ __forceinline__ void fma2(ull& d, ull a, ull b) {
    asm("fma.rn.f32x2 %0, %1, %2, %0;" : "+l"(d) : "l"(a), "l"(b));
}
__device__ __forceinline__ void cpasync16(u32 dst, const void* src) {
    asm volatile("cp.async.ca.shared.global [%0], [%1], 16;" :: "r"(dst), "l"(src) : "memory");
}
__device__ __forceinline__ void cpcommit() { asm volatile("cp.async.commit_group;" ::: "memory"); }
__device__ __forceinline__ void cpwait0()  { asm volatile("cp.async.wait_group 0;" ::: "memory"); }

// ---------------- combined prep: edges + all weight relayouts, ONE launch ----
// grid = 1024 x 256 threads. Every warp handles one node's edge row; thread
// ranges additionally cover the three weight relayouts.
__global__ void prep_all(const float* __restrict__ edges,
                         const float* __restrict__ W_msg,
                         const float* __restrict__ W_ih,
                         const float* __restrict__ W_hh,
                         const float* __restrict__ Wg,
                         const float* __restrict__ We) {
    const int gid  = blockIdx.x * blockDim.x + threadIdx.x;
    const int warp = gid >> 5;
    const int lane = threadIdx.x & 31;

    // ---- edge compaction (warp per node) ----
    if (warp < NODES) {
        int p = warp;
        float4 v = ((const float4*)edges)[(size_t)p * NN + lane];
        float vv[4] = {v.x, v.y, v.z, v.w};
        int nl = (vv[0]!=0.f) + (vv[1]!=0.f) + (vv[2]!=0.f) + (vv[3]!=0.f);
        int inc = nl;
        #pragma unroll
        for (int off = 1; off < 32; off <<= 1) {
            int t = __shfl_up_sync(0xFFFFFFFFu, inc, off);
            if (lane >= off) inc += t;
        }
        int excl = inc - nl;
        int total = __shfl_sync(0xFFFFFFFFu, inc, 31);
        int c = excl;
        #pragma unroll
        for (int f = 0; f < EFN; f++) {
            if (vv[f] != 0.f && c < KMAX) {
                g_nbr[p*KMAX + c] = lane;
                g_typ[p*KMAX + c] = f;
                g_wgt[p*KMAX + c] = vv[f];
                c++;
            }
        }
        if (lane == 0) g_cnt[p] = (total < KMAX) ? total : KMAX;
    }

    // ---- weight relayouts (disjoint gid ranges) ----
    const int NWT = EFN*HH*MM;            // 40000
    if (gid < NWT) {
        int f = gid / (HH*MM);
        int rem = gid % (HH*MM);
        int k = rem / MM;
        int m = rem % MM;
        g_Wm[gid] = W_msg[(m*HH + k)*EFN + f];
    } else if (gid < NWT + HH*HH) {       // 10000 (k,h) entries
        int t = gid - NWT;
        int k = t / HH, h = t % HH;
        float* dst = g_Wp + (size_t)t*6;
        dst[0] = W_ih[(h)*HH + k];
        dst[1] = W_ih[(100+h)*HH + k];
        dst[2] = W_ih[(200+h)*HH + k];
        dst[3] = W_hh[(h)*HH + k];
        dst[4] = W_hh[(100+h)*HH + k];
        dst[5] = W_hh[(200+h)*HH + k];
    } else if (gid < NWT + HH*HH + 140*HH) {
        int t = gid - NWT - HH*HH;
        int k = t / HH, h = t % HH;
        float wg = Wg[k*HH + h];
        float we = (k < HH) ? We[k*HH + h] : 0.0f;
        g_WgeD[t] = make_ulonglong2(packdup(wg), packdup(we));
    }
}

// ---------------- fused: 3 passes + readout, one block per batch ----------
__global__ __launch_bounds__(NTHR, 2) void fused_kernel(
        const float* __restrict__ nodes,
        const float* __restrict__ b_ih, const float* __restrict__ b_hh,
        const float* __restrict__ bg,   const float* __restrict__ be,
        const float* __restrict__ Wo,   const float* __restrict__ bo,
        float* __restrict__ out) {
    __shared__ __align__(16) float sh_h[HH*NN];          // [k][n] 12.8KB
    __shared__ __align__(16) float sh_T[EFN*HH*TPAD];    // 64KB: T; GRU weight bufs overlay
    __shared__ __align__(16) float sh_msg[HH*NN];        // [k][n] 12.8KB
    __shared__ __align__(16) float sh_x[FF*NN];          // 5.1KB
    __shared__ int   sh_nbr[NN][KMAX];
    __shared__ int   sh_typ[NN][KMAX];
    __shared__ float sh_wgt[NN][KMAX];
    __shared__ int   sh_cnt[NN];
    __shared__ float sh_part[4*HH];
    __shared__ float sh_acc[HH];

    const int b   = blockIdx.x;
    const int tid = threadIdx.x;
    const int p0  = b * NN;

    // edge meta
    if (tid < NN) sh_cnt[tid] = g_cnt[p0 + tid];
    else if (tid >= 32 && tid < 32 + NN*KMAX) {
        int t = tid - 32; int n = t >> 3, e = t & 7;
        sh_nbr[n][e] = g_nbr[(p0+n)*KMAX + e];
        sh_typ[n][e] = g_typ[(p0+n)*KMAX + e];
        sh_wgt[n][e] = g_wgt[(p0+n)*KMAX + e];
    }
    // hidden init: [nodes | 0]
    for (int idx = tid; idx < HH*NN; idx += NTHR) {
        int k = idx >> 5, n = idx & 31;
        sh_h[idx] = (k < FF) ? nodes[(size_t)(p0+n)*FF + k] : 0.0f;
    }
    __syncthreads();

    const int hh = (tid < 400) ? (tid % 100) : 0;
    const int ng = (tid < 400) ? (tid / 100) : 0;

    // hoisted GRU biases (constant across passes)
    float brz = 0.f, bzz = 0.f, bin = 0.f, bhn = 0.f;
    if (tid < 400) {
        brz = b_ih[hh]       + b_hh[hh];
        bzz = b_ih[100 + hh] + b_hh[100 + hh];
        bin = b_ih[200 + hh];
        bhn = b_hh[200 + hh];
    }

    for (int pass = 0; pass < 3; pass++) {
        // ---- T[f][m][n] = sum_k Wm[f][k][m] * h[k][n] ----
        if (tid < 400) {
            const int f = tid / 100, m = tid - f*100;
            ull acc[16];
            #pragma unroll
            for (int j = 0; j < 16; j++) acc[j] = 0ull;
            const float* W = g_Wm + (size_t)(f*HH)*MM + m;
            for (int k = 0; k < HH; k++) {
                ull w = packdup(W[k*MM]);
                const ulonglong2* hp = (const ulonglong2*)(sh_h + k*NN);
                ulonglong2 v0 = hp[0], v1 = hp[1], v2 = hp[2], v3 = hp[3];
                fma2(acc[0], w, v0.x); fma2(acc[1], w, v0.y);
                fma2(acc[2], w, v1.x); fma2(acc[3], w, v1.y);
                fma2(acc[4], w, v2.x); fma2(acc[5], w, v2.y);
                fma2(acc[6], w, v3.x); fma2(acc[7], w, v3.y);
                ulonglong2 v4 = hp[4], v5 = hp[5], v6 = hp[6], v7 = hp[7];
                fma2(acc[8],  w, v4.x); fma2(acc[9],  w, v4.y);
                fma2(acc[10], w, v5.x); fma2(acc[11], w, v5.y);
                fma2(acc[12], w, v6.x); fma2(acc[13], w, v6.y);
                fma2(acc[14], w, v7.x); fma2(acc[15], w, v7.y);
            }
            ulonglong2* Trow = (ulonglong2*)(sh_T + (size_t)(f*MM + m)*TPAD);
            #pragma unroll
            for (int j = 0; j < 8; j++) Trow[j] = make_ulonglong2(acc[2*j], acc[2*j+1]);
        }
        __syncthreads();

        // ---- gather: msg[m][n] = sum_e w_e * T[f_e][m][g_e] -> sh_msg ----
        if (tid < 400) {
            const int m = tid >> 2;
            const int n0 = (tid & 3) * 8;
            float res[8];
            #pragma unroll
            for (int j = 0; j < 8; j++) {
                int n = n0 + j;
                int c = sh_cnt[n];
                float s = 0.f;
                for (int e = 0; e < c; e++) {
                    s += sh_wgt[n][e] *
                         sh_T[(size_t)(sh_typ[n][e]*MM + m)*TPAD + sh_nbr[n][e]];
                }
                res[j] = s;
            }
            float4* dst = (float4*)(sh_msg + (size_t)m*NN + n0);
            dst[0] = make_float4(res[0], res[1], res[2], res[3]);
            dst[1] = make_float4(res[4], res[5], res[6], res[7]);
        }
        __syncthreads();   // msg visible; sh_T free for weight buffers

        // ---- GRU: double-buffered cp.async weight tiles ----
        ull accA[4], accB[4], accC[4], accD[4];
        #pragma unroll
        for (int j = 0; j < 4; j++) { accA[j]=0; accB[j]=0; accC[j]=0; accD[j]=0; }

        // prefetch tile 0 into buf 0
        {
            u32 dstb = (u32)__cvta_generic_to_shared(sh_T);
            const float4* src = (const float4*)g_Wp;
            for (int i = tid; i < KTILE*150; i += NTHR)
                cpasync16(dstb + i*16, src + i);
            cpcommit();
        }

        for (int t = 0; t < NTILE; t++) {
            const int kbase = t * KTILE;
            const int kt = (HH - kbase < KTILE) ? (HH - kbase) : KTILE;
            float* buf = sh_T + (t & 1) * (KTILE*600);
            cpwait0();
            __syncthreads();
            if (t + 1 < NTILE) {
                const int nb = (t+1) * KTILE;
                const int nkt = (HH - nb < KTILE) ? (HH - nb) : KTILE;
                float* nbuf = sh_T + ((t+1) & 1) * (KTILE*600);
                u32 dstb = (u32)__cvta_generic_to_shared(nbuf);
                const float4* src = (const float4*)(g_Wp + (size_t)nb*600);
                for (int i = tid; i < nkt*150; i += NTHR)
                    cpasync16(dstb + i*16, src + i);
                cpcommit();
            }
            if (tid < 400) {
                for (int kk = 0; kk < kt; kk++) {
                    const int k = kbase + kk;
                    const ull* wp = (const ull*)(buf + kk*600 + hh*6);
                    ull w01 = wp[0], w23 = wp[1], w45 = wp[2];
                    float wir, wiz, win, whr, whz, whn;
                    unpack2(w01, wir, wiz);
                    unpack2(w23, win, whr);
                    unpack2(w45, whz, whn);
                    ull dIR = packdup(wir), dIZ = packdup(wiz), dIN = packdup(win);
                    ull dHR = packdup(whr), dHZ = packdup(whz), dHN = packdup(whn);
                    const ulonglong2* mp = (const ulonglong2*)(sh_msg + (size_t)k*NN + ng*8);
                    const ulonglong2* hp = (const ulonglong2*)(sh_h + k*NN + ng*8);
                    ulonglong2 m01 = mp[0], m23 = mp[1];
                    ulonglong2 h01 = hp[0], h23 = hp[1];
                    fma2(accA[0], dIR, m01.x); fma2(accA[0], dHR, h01.x);
                    fma2(accA[1], dIR, m01.y); fma2(accA[1], dHR, h01.y);
                    fma2(accA[2], dIR, m23.x); fma2(accA[2], dHR, h23.x);
                    fma2(accA[3], dIR, m23.y); fma2(accA[3], dHR, h23.y);
                    fma2(accB[0], dIZ, m01.x); fma2(accB[0], dHZ, h01.x);
                    fma2(accB[1], dIZ, m01.y); fma2(accB[1], dHZ, h01.y);
                    fma2(accB[2], dIZ, m23.x); fma2(accB[2], dHZ, h23.x);
                    fma2(accB[3], dIZ, m23.y); fma2(accB[3], dHZ, h23.y);
                    fma2(accC[0], dIN, m01.x); fma2(accC[1], dIN, m01.y);
                    fma2(accC[2], dIN, m23.x); fma2(accC[3], dIN, m23.y);
                    fma2(accD[0], dHN, h01.x); fma2(accD[1], dHN, h01.y);
                    fma2(accD[2], dHN, h23.x); fma2(accD[3], dHN, h23.y);
                }
            }
        }

        // previous h values for this (h, 8 nodes)
        ull hv[4];
        if (tid < 400) {
            const ulonglong2* hvp = (const ulonglong2*)(sh_h + hh*NN + ng*8);
            ulonglong2 a = hvp[0], c = hvp[1];
            hv[0] = a.x; hv[1] = a.y; hv[2] = c.x; hv[3] = c.y;
        }
        __syncthreads();   // all reads of sh_h / sh_msg done

        if (tid < 400) {
            float o[8];
            #pragma unroll
            for (int j = 0; j < 4; j++) {
                float a0, a1, zb0, zb1, c0, c1, d0, d1, h0, h1;
                unpack2(accA[j], a0, a1);
                unpack2(accB[j], zb0, zb1);
                unpack2(accC[j], c0, c1);
                unpack2(accD[j], d0, d1);
                unpack2(hv[j], h0, h1);
                int nA = ng*8 + 2*j, nB = nA + 1;
                {
                    float r = sigmf(a0 + brz);
                    float z = sigmf(zb0 + bzz);
                    float nv = tanhf(c0 + bin + r*(d0 + bhn));
                    o[2*j]   = (sh_cnt[nA] == 0) ? h0 : (1.0f - z)*nv + z*h0;
                }
                {
                    float r = sigmf(a1 + brz);
                    float z = sigmf(zb1 + bzz);
                    float nv = tanhf(c1 + bin + r*(d1 + bhn));
                    o[2*j+1] = (sh_cnt[nB] == 0) ? h1 : (1.0f - z)*nv + z*h1;
                }
            }
            float4* dst = (float4*)(sh_h + hh*NN + ng*8);
            dst[0] = make_float4(o[0], o[1], o[2], o[3]);
            dst[1] = make_float4(o[4], o[5], o[6], o[7]);
        }
        __syncthreads();
    }

    // ---- readout ----
    for (int idx = tid; idx < NN*FF; idx += NTHR) {
        int n = idx / FF, k = idx % FF;
        sh_x[k*NN + n] = nodes[(size_t)(p0+n)*FF + k];
    }
    __syncthreads();

    if (tid < 400) {
        ull ga[4], ev[4];
        #pragma unroll
        for (int j = 0; j < 4; j++) { ga[j] = 0; ev[j] = 0; }
        const ulonglong2* WD = g_WgeD + hh;
        for (int k = 0; k < HH; k++) {
            ulonglong2 w = WD[k*HH];
            const ulonglong2* hp = (const ulonglong2*)(sh_h + k*NN + ng*8);
            ulonglong2 a = hp[0], c = hp[1];
            fma2(ga[0], w.x, a.x); fma2(ga[1], w.x, a.y);
            fma2(ga[2], w.x, c.x); fma2(ga[3], w.x, c.y);
            fma2(ev[0], w.y, a.x); fma2(ev[1], w.y, a.y);
            fma2(ev[2], w.y, c.x); fma2(ev[3], w.y, c.y);
        }
        for (int k = 0; k < FF; k++) {
            ulonglong2 w = WD[(HH + k)*HH];
            const ulonglong2* xp = (const ulonglong2*)(sh_x + k*NN + ng*8);
            ulonglong2 a = xp[0], c = xp[1];
            fma2(ga[0], w.x, a.x); fma2(ga[1], w.x, a.y);
            fma2(ga[2], w.x, c.x); fma2(ga[3], w.x, c.y);
        }
        float bgv = bg[hh], bev = be[hh];
        float s = 0.f;
        #pragma unroll
        for (int j = 0; j < 4; j++) {
            float gl, gh_, el, eh;
            unpack2(ga[j], gl, gh_);
            unpack2(ev[j], el, eh);
            int nA = ng*8 + 2*j, nB = nA + 1;
            if (sh_cnt[nA] != 0) s += sigmf(gl + bgv) * (el + bev);
            if (sh_cnt[nB] != 0) s += sigmf(gh_ + bgv) * (eh + bev);
        }
        sh_part[ng*HH + hh] = s;
    }
    __syncthreads();
    if (tid < HH)
        sh_acc[tid] = sh_part[tid] + sh_part[HH + tid] + sh_part[2*HH + tid] + sh_part[3*HH + tid];
    __syncthreads();

    if (tid < OUTD) {
        float v = bo[tid];
        #pragma unroll 4
        for (int k = 0; k < HH; k++) v += sh_acc[k] * Wo[k*OUTD + tid];
        out[(size_t)b*OUTD + tid] = v;
    }
}

// ---------------- launcher ----------------
extern "C" void kernel_launch(void* const* d_in, const int* in_sizes, int n_in,
                              void* d_out, int out_size) {
    const float* nodes = (const float*)d_in[0];
    const float* edges = (const float*)d_in[1];
    const float* W_msg = (const float*)d_in[2];
    const float* W_ih  = (const float*)d_in[3];
    const float* W_hh  = (const float*)d_in[4];
    const float* b_ih  = (const float*)d_in[5];
    const float* b_hh  = (const float*)d_in[6];
    const float* Wg    = (const float*)d_in[7];
    const float* bg    = (const float*)d_in[8];
    const float* We    = (const float*)d_in[9];
    const float* be    = (const float*)d_in[10];
    const float* Wo    = (const float*)d_in[11];
    const float* bo    = (const float*)d_in[12];
    float* out = (float*)d_out;

    // ONE prep launch (edges need 8192 warps = 262144 threads = 1024 blocks)
    prep_all<<<1024, 256>>>(edges, W_msg, W_ih, W_hh, Wg, We);
    fused_kernel<<<BB, NTHR>>>(nodes, b_ih, b_hh, bg, be, Wo, bo, out);
}

// round 13
// speedup vs baseline: 1.3624x; 1.0162x over previous
#include <cuda_runtime.h>
#include <math.h>
#include <stdint.h>

#define BB    256
#define NN    32
#define FF    40
#define HH    100
#define MM    100
#define EFN   4
#define OUTD  128
#define H3    300
#define KMAX  8
#define NODES (BB*NN)   // 8192
#define TPAD  40        // T row stride (floats)
#define NTHR  416
#define KTILE 12        // GRU k-tile
#define NTILE 9         // ceil(100/12)

typedef unsigned long long ull;
typedef unsigned int u32;

// ---------------- device scratch ----------------
__device__ __align__(16) float g_Wm[EFN*HH*MM];      // [f][k][m]
__device__ __align__(16) float g_Wp[HH*HH*6];        // [k][h][6] = ihR,ihZ,ihN,hhR,hhZ,hhN
__device__ __align__(16) ulonglong2 g_WgeD[140*HH];  // [k][h] = {dup(wg), dup(we)}
__device__ int   g_nbr[NODES*KMAX];
__device__ int   g_typ[NODES*KMAX];
__device__ float g_wgt[NODES*KMAX];
__device__ int   g_cnt[NODES];

__device__ __forceinline__ float sigmf(float x) { return 1.0f / (1.0f + expf(-x)); }
__device__ __forceinline__ ull packdup(float w) {
    ull r; asm("mov.b64 %0,{%1,%1};" : "=l"(r) : "f"(w)); return r;
}
__device__ __forceinline__ void unpack2(ull v, float& lo, float& hi) {
    asm("mov.b64 {%0,%1},%2;" : "=f"(lo), "=f"(hi) : "l"(v));
}
__device__ __forceinline__ void fma2(ull& d, ull a, ull b) {
    asm("fma.rn.f32x2 %0, %1, %2, %0;" : "+l"(d) : "l"(a), "l"(b));
}
__device__ __forceinline__ void cpasync16(u32 dst, const void* src) {
    asm volatile("cp.async.ca.shared.global [%0], [%1], 16;" :: "r"(dst), "l"(src) : "memory");
}
__device__ __forceinline__ void cpcommit() { asm volatile("cp.async.commit_group;" ::: "memory"); }
__device__ __forceinline__ void cpwait0()  { asm volatile("cp.async.wait_group 0;" ::: "memory"); }

// ---------------- combined prep: edges + all weight relayouts, ONE launch ----
__global__ void prep_all(const float* __restrict__ edges,
                         const float* __restrict__ W_msg,
                         const float* __restrict__ W_ih,
                         const float* __restrict__ W_hh,
                         const float* __restrict__ Wg,
                         const float* __restrict__ We) {
    const int gid  = blockIdx.x * blockDim.x + threadIdx.x;
    const int warp = gid >> 5;
    const int lane = threadIdx.x & 31;

    // ---- edge compaction (warp per node) ----
    if (warp < NODES) {
        int p = warp;
        float4 v = ((const float4*)edges)[(size_t)p * NN + lane];
        float vv[4] = {v.x, v.y, v.z, v.w};
        int nl = (vv[0]!=0.f) + (vv[1]!=0.f) + (vv[2]!=0.f) + (vv[3]!=0.f);
        int inc = nl;
        #pragma unroll
        for (int off = 1; off < 32; off <<= 1) {
            int t = __shfl_up_sync(0xFFFFFFFFu, inc, off);
            if (lane >= off) inc += t;
        }
        int excl = inc - nl;
        int total = __shfl_sync(0xFFFFFFFFu, inc, 31);
        int c = excl;
        #pragma unroll
        for (int f = 0; f < EFN; f++) {
            if (vv[f] != 0.f && c < KMAX) {
                g_nbr[p*KMAX + c] = lane;
                g_typ[p*KMAX + c] = f;
                g_wgt[p*KMAX + c] = vv[f];
                c++;
            }
        }
        if (lane == 0) g_cnt[p] = (total < KMAX) ? total : KMAX;
    }

    // ---- weight relayouts (disjoint gid ranges) ----
    const int NWT = EFN*HH*MM;            // 40000
    if (gid < NWT) {
        int f = gid / (HH*MM);
        int rem = gid % (HH*MM);
        int k = rem / MM;
        int m = rem % MM;
        g_Wm[gid] = W_msg[(m*HH + k)*EFN + f];
    } else if (gid < NWT + HH*HH) {       // 10000 (k,h) entries
        int t = gid - NWT;
        int k = t / HH, h = t % HH;
        float* dst = g_Wp + (size_t)t*6;
        dst[0] = W_ih[(h)*HH + k];
        dst[1] = W_ih[(100+h)*HH + k];
        dst[2] = W_ih[(200+h)*HH + k];
        dst[3] = W_hh[(h)*HH + k];
        dst[4] = W_hh[(100+h)*HH + k];
        dst[5] = W_hh[(200+h)*HH + k];
    } else if (gid < NWT + HH*HH + 140*HH) {
        int t = gid - NWT - HH*HH;
        int k = t / HH, h = t % HH;
        float wg = Wg[k*HH + h];
        float we = (k < HH) ? We[k*HH + h] : 0.0f;
        g_WgeD[t] = make_ulonglong2(packdup(wg), packdup(we));
    }
}

// ---------------- fused: 3 passes + readout, one block per batch ----------
__global__ __launch_bounds__(NTHR, 2) void fused_kernel(
        const float* __restrict__ nodes,
        const float* __restrict__ b_ih, const float* __restrict__ b_hh,
        const float* __restrict__ bg,   const float* __restrict__ be,
        const float* __restrict__ Wo,   const float* __restrict__ bo,
        float* __restrict__ out) {
    __shared__ __align__(16) float sh_h[HH*NN];          // [k][n] 12.8KB
    __shared__ __align__(16) float sh_T[EFN*HH*TPAD];    // 64KB: T; GRU weight bufs overlay
    __shared__ __align__(16) float sh_msg[HH*NN];        // [k][n] 12.8KB
    __shared__ __align__(16) float sh_x[FF*NN];          // 5.1KB
    __shared__ int   sh_nbr[NN][KMAX];
    __shared__ int   sh_typ[NN][KMAX];
    __shared__ float sh_wgt[NN][KMAX];
    __shared__ int   sh_cnt[NN];
    __shared__ float sh_part[4*HH];
    __shared__ float sh_acc[HH];

    const int b   = blockIdx.x;
    const int tid = threadIdx.x;
    const int p0  = b * NN;

    // edge meta
    if (tid < NN) sh_cnt[tid] = g_cnt[p0 + tid];
    else if (tid >= 32 && tid < 32 + NN*KMAX) {
        int t = tid - 32; int n = t >> 3, e = t & 7;
        sh_nbr[n][e] = g_nbr[(p0+n)*KMAX + e];
        sh_typ[n][e] = g_typ[(p0+n)*KMAX + e];
        sh_wgt[n][e] = g_wgt[(p0+n)*KMAX + e];
    }
    // hidden init: [nodes | 0]
    for (int idx = tid; idx < HH*NN; idx += NTHR) {
        int k = idx >> 5, n = idx & 31;
        sh_h[idx] = (k < FF) ? nodes[(size_t)(p0+n)*FF + k] : 0.0f;
    }
    __syncthreads();

    const int hh = (tid < 400) ? (tid % 100) : 0;
    const int ng = (tid < 400) ? (tid / 100) : 0;

    // hoisted GRU biases (constant across passes)
    float brz = 0.f, bzz = 0.f, bin = 0.f, bhn = 0.f;
    if (tid < 400) {
        brz = b_ih[hh]       + b_hh[hh];
        bzz = b_ih[100 + hh] + b_hh[100 + hh];
        bin = b_ih[200 + hh];
        bhn = b_hh[200 + hh];
    }

    for (int pass = 0; pass < 3; pass++) {
        // ---- T[f][m][n] = sum_k Wm[f][k][m] * h[k][n] -- 4m x 8n register tile ----
        if (tid < 400) {
            const int f  = tid / 100, r = tid - f*100;
            const int mq = r >> 2;          // m base = mq*4
            const int nt = r & 3;           // node octet: nt*8
            ull acc[4][4];
            #pragma unroll
            for (int i = 0; i < 4; i++)
                #pragma unroll
                for (int j = 0; j < 4; j++) acc[i][j] = 0ull;
            const float4* W4 = (const float4*)(g_Wm + (size_t)(f*HH)*MM);
            for (int k = 0; k < HH; k++) {
                float4 wv = W4[k*25 + mq];
                ull w0 = packdup(wv.x), w1 = packdup(wv.y);
                ull w2 = packdup(wv.z), w3 = packdup(wv.w);
                const ulonglong2* hp = (const ulonglong2*)(sh_h + k*NN + nt*8);
                ulonglong2 d0 = hp[0], d1 = hp[1];
                fma2(acc[0][0], w0, d0.x); fma2(acc[0][1], w0, d0.y);
                fma2(acc[0][2], w0, d1.x); fma2(acc[0][3], w0, d1.y);
                fma2(acc[1][0], w1, d0.x); fma2(acc[1][1], w1, d0.y);
                fma2(acc[1][2], w1, d1.x); fma2(acc[1][3], w1, d1.y);
                fma2(acc[2][0], w2, d0.x); fma2(acc[2][1], w2, d0.y);
                fma2(acc[2][2], w2, d1.x); fma2(acc[2][3], w2, d1.y);
                fma2(acc[3][0], w3, d0.x); fma2(acc[3][1], w3, d0.y);
                fma2(acc[3][2], w3, d1.x); fma2(acc[3][3], w3, d1.y);
            }
            #pragma unroll
            for (int mi = 0; mi < 4; mi++) {
                ulonglong2* dst = (ulonglong2*)(sh_T + (size_t)(f*MM + mq*4 + mi)*TPAD + nt*8);
                dst[0] = make_ulonglong2(acc[mi][0], acc[mi][1]);
                dst[1] = make_ulonglong2(acc[mi][2], acc[mi][3]);
            }
        }
        __syncthreads();

        // ---- gather: msg[m][n] = sum_e w_e * T[f_e][m][g_e] -> sh_msg ----
        if (tid < 400) {
            const int m = tid >> 2;
            const int n0 = (tid & 3) * 8;
            float res[8];
            #pragma unroll
            for (int j = 0; j < 8; j++) {
                int n = n0 + j;
                int c = sh_cnt[n];
                float s = 0.f;
                for (int e = 0; e < c; e++) {
                    s += sh_wgt[n][e] *
                         sh_T[(size_t)(sh_typ[n][e]*MM + m)*TPAD + sh_nbr[n][e]];
                }
                res[j] = s;
            }
            float4* dst = (float4*)(sh_msg + (size_t)m*NN + n0);
            dst[0] = make_float4(res[0], res[1], res[2], res[3]);
            dst[1] = make_float4(res[4], res[5], res[6], res[7]);
        }
        __syncthreads();   // msg visible; sh_T free for weight buffers

        // ---- GRU: double-buffered cp.async weight tiles ----
        ull accA[4], accB[4], accC[4], accD[4];
        #pragma unroll
        for (int j = 0; j < 4; j++) { accA[j]=0; accB[j]=0; accC[j]=0; accD[j]=0; }

        // prefetch tile 0 into buf 0
        {
            u32 dstb = (u32)__cvta_generic_to_shared(sh_T);
            const float4* src = (const float4*)g_Wp;
            for (int i = tid; i < KTILE*150; i += NTHR)
                cpasync16(dstb + i*16, src + i);
            cpcommit();
        }

        for (int t = 0; t < NTILE; t++) {
            const int kbase = t * KTILE;
            const int kt = (HH - kbase < KTILE) ? (HH - kbase) : KTILE;
            float* buf = sh_T + (t & 1) * (KTILE*600);
            cpwait0();
            __syncthreads();
            if (t + 1 < NTILE) {
                const int nb = (t+1) * KTILE;
                const int nkt = (HH - nb < KTILE) ? (HH - nb) : KTILE;
                float* nbuf = sh_T + ((t+1) & 1) * (KTILE*600);
                u32 dstb = (u32)__cvta_generic_to_shared(nbuf);
                const float4* src = (const float4*)(g_Wp + (size_t)nb*600);
                for (int i = tid; i < nkt*150; i += NTHR)
                    cpasync16(dstb + i*16, src + i);
                cpcommit();
            }
            if (tid < 400) {
                for (int kk = 0; kk < kt; kk++) {
                    const int k = kbase + kk;
                    const ull* wp = (const ull*)(buf + kk*600 + hh*6);
                    ull w01 = wp[0], w23 = wp[1], w45 = wp[2];
                    float wir, wiz, win, whr, whz, whn;
                    unpack2(w01, wir, wiz);
                    unpack2(w23, win, whr);
                    unpack2(w45, whz, whn);
                    ull dIR = packdup(wir), dIZ = packdup(wiz), dIN = packdup(win);
                    ull dHR = packdup(whr), dHZ = packdup(whz), dHN = packdup(whn);
                    const ulonglong2* mp = (const ulonglong2*)(sh_msg + (size_t)k*NN + ng*8);
                    const ulonglong2* hp = (const ulonglong2*)(sh_h + k*NN + ng*8);
                    ulonglong2 m01 = mp[0], m23 = mp[1];
                    ulonglong2 h01 = hp[0], h23 = hp[1];
                    fma2(accA[0], dIR, m01.x); fma2(accA[0], dHR, h01.x);
                    fma2(accA[1], dIR, m01.y); fma2(accA[1], dHR, h01.y);
                    fma2(accA[2], dIR, m23.x); fma2(accA[2], dHR, h23.x);
                    fma2(accA[3], dIR, m23.y); fma2(accA[3], dHR, h23.y);
                    fma2(accB[0], dIZ, m01.x); fma2(accB[0], dHZ, h01.x);
                    fma2(accB[1], dIZ, m01.y); fma2(accB[1], dHZ, h01.y);
                    fma2(accB[2], dIZ, m23.x); fma2(accB[2], dHZ, h23.x);
                    fma2(accB[3], dIZ, m23.y); fma2(accB[3], dHZ, h23.y);
                    fma2(accC[0], dIN, m01.x); fma2(accC[1], dIN, m01.y);
                    fma2(accC[2], dIN, m23.x); fma2(accC[3], dIN, m23.y);
                    fma2(accD[0], dHN, h01.x); fma2(accD[1], dHN, h01.y);
                    fma2(accD[2], dHN, h23.x); fma2(accD[3], dHN, h23.y);
                }
            }
        }

        // previous h values for this (h, 8 nodes)
        ull hv[4];
        if (tid < 400) {
            const ulonglong2* hvp = (const ulonglong2*)(sh_h + hh*NN + ng*8);
            ulonglong2 a = hvp[0], c = hvp[1];
            hv[0] = a.x; hv[1] = a.y; hv[2] = c.x; hv[3] = c.y;
        }
        __syncthreads();   // all reads of sh_h / sh_msg done

        if (tid < 400) {
            float o[8];
            #pragma unroll
            for (int j = 0; j < 4; j++) {
                float a0, a1, zb0, zb1, c0, c1, d0, d1, h0, h1;
                unpack2(accA[j], a0, a1);
                unpack2(accB[j], zb0, zb1);
                unpack2(accC[j], c0, c1);
                unpack2(accD[j], d0, d1);
                unpack2(hv[j], h0, h1);
                int nA = ng*8 + 2*j, nB = nA + 1;
                {
                    float r = sigmf(a0 + brz);
                    float z = sigmf(zb0 + bzz);
                    float nv = tanhf(c0 + bin + r*(d0 + bhn));
                    o[2*j]   = (sh_cnt[nA] == 0) ? h0 : (1.0f - z)*nv + z*h0;
                }
                {
                    float r = sigmf(a1 + brz);
                    float z = sigmf(zb1 + bzz);
                    float nv = tanhf(c1 + bin + r*(d1 + bhn));
                    o[2*j+1] = (sh_cnt[nB] == 0) ? h1 : (1.0f - z)*nv + z*h1;
                }
            }
            float4* dst = (float4*)(sh_h + hh*NN + ng*8);
            dst[0] = make_float4(o[0], o[1], o[2], o[3]);
            dst[1] = make_float4(o[4], o[5], o[6], o[7]);
        }
        __syncthreads();
    }

    // ---- readout ----
    for (int idx = tid; idx < NN*FF; idx += NTHR) {
        int n = idx / FF, k = idx % FF;
        sh_x[k*NN + n] = nodes[(size_t)(p0+n)*FF + k];
    }
    __syncthreads();

    if (tid < 400) {
        ull ga[4], ev[4];
        #pragma unroll
        for (int j = 0; j < 4; j++) { ga[j] = 0; ev[j] = 0; }
        const ulonglong2* WD = g_WgeD + hh;
        for (int k = 0; k < HH; k++) {
            ulonglong2 w = WD[k*HH];
            const ulonglong2* hp = (const ulonglong2*)(sh_h + k*NN + ng*8);
            ulonglong2 a = hp[0], c = hp[1];
            fma2(ga[0], w.x, a.x); fma2(ga[1], w.x, a.y);
            fma2(ga[2], w.x, c.x); fma2(ga[3], w.x, c.y);
            fma2(ev[0], w.y, a.x); fma2(ev[1], w.y, a.y);
            fma2(ev[2], w.y, c.x); fma2(ev[3], w.y, c.y);
        }
        for (int k = 0; k < FF; k++) {
            ulonglong2 w = WD[(HH + k)*HH];
            const ulonglong2* xp = (const ulonglong2*)(sh_x + k*NN + ng*8);
            ulonglong2 a = xp[0], c = xp[1];
            fma2(ga[0], w.x, a.x); fma2(ga[1], w.x, a.y);
            fma2(ga[2], w.x, c.x); fma2(ga[3], w.x, c.y);
        }
        float bgv = bg[hh], bev = be[hh];
        float s = 0.f;
        #pragma unroll
        for (int j = 0; j < 4; j++) {
            float gl, gh_, el, eh;
            unpack2(ga[j], gl, gh_);
            unpack2(ev[j], el, eh);
            int nA = ng*8 + 2*j, nB = nA + 1;
            if (sh_cnt[nA] != 0) s += sigmf(gl + bgv) * (el + bev);
            if (sh_cnt[nB] != 0) s += sigmf(gh_ + bgv) * (eh + bev);
        }
        sh_part[ng*HH + hh] = s;
    }
    __syncthreads();
    if (tid < HH)
        sh_acc[tid] = sh_part[tid] + sh_part[HH + tid] + sh_part[2*HH + tid] + sh_part[3*HH + tid];
    __syncthreads();

    if (tid < OUTD) {
        float v = bo[tid];
        #pragma unroll 4
        for (int k = 0; k < HH; k++) v += sh_acc[k] * Wo[k*OUTD + tid];
        out[(size_t)b*OUTD + tid] = v;
    }
}

// ---------------- launcher ----------------
extern "C" void kernel_launch(void* const* d_in, const int* in_sizes, int n_in,
                              void* d_out, int out_size) {
    const float* nodes = (const float*)d_in[0];
    const float* edges = (const float*)d_in[1];
    const float* W_msg = (const float*)d_in[2];
    const float* W_ih  = (const float*)d_in[3];
    const float* W_hh  = (const float*)d_in[4];
    const float* b_ih  = (const float*)d_in[5];
    const float* b_hh  = (const float*)d_in[6];
    const float* Wg    = (const float*)d_in[7];
    const float* bg    = (const float*)d_in[8];
    const float* We    = (const float*)d_in[9];
    const float* be    = (const float*)d_in[10];
    const float* Wo    = (const float*)d_in[11];
    const float* bo    = (const float*)d_in[12];
    float* out = (float*)d_out;

    prep_all<<<1024, 256>>>(edges, W_msg, W_ih, W_hh, Wg, We);
    fused_kernel<<<BB, NTHR>>>(nodes, b_ih, b_hh, bg, be, Wo, bo, out);
}